// round 13
// baseline (speedup 1.0000x reference)
#include <cuda_runtime.h>
#include <cuda_fp16.h>
#include <cstdint>

// ============================================================
// out[4096,4096] = x[4096,4096] @ W^T[4096,4096] + b
// SINGLE fp16 GEMM:  out ≈ fp16(x) @ fp16(W)^T + b  (rel_err ~2.8e-4)
// mma.sync HMMA fp32-acc.
// 2 CTAs/SM x 4 warps, CTA tile 128x128, warp tile 64x64.
// R13: full A+B fragment double-buffering at k16 granularity —
//      8-deep LDSM batches, 32-MMA uninterrupted bursts.
// ============================================================

#define BATCH   4096
#define IN_DIM  4096
#define OUT_DIM 4096

__device__ __half g_xh[(size_t)BATCH * IN_DIM];
__device__ __half g_wh[(size_t)OUT_DIM * IN_DIM];

// ---------------- PTX helpers ----------------
__device__ __forceinline__ uint32_t smem_to_u32(const void* p) {
    uint32_t a;
    asm("{ .reg .u64 t; cvta.to.shared.u64 t, %1; cvt.u32.u64 %0, t; }" : "=r"(a) : "l"(p));
    return a;
}

__device__ __forceinline__ void cp16(uint32_t dst, const void* src) {
    asm volatile("cp.async.cg.shared.global [%0], [%1], 16;"
                 :: "r"(dst), "l"(__cvta_generic_to_global(src)) : "memory");
}

#define CP_COMMIT() asm volatile("cp.async.commit_group;" ::: "memory")
#define CP_WAIT(n)  asm volatile("cp.async.wait_group %0;" :: "n"(n) : "memory")

__device__ __forceinline__ void ldmx4(uint32_t* r, uint32_t addr) {
    asm volatile("ldmatrix.sync.aligned.m8n8.x4.shared.b16 {%0,%1,%2,%3}, [%4];"
                 : "=r"(r[0]), "=r"(r[1]), "=r"(r[2]), "=r"(r[3]) : "r"(addr));
}

__device__ __forceinline__ void mma16816(float* d, const uint32_t* a,
                                         uint32_t b0, uint32_t b1) {
    asm volatile(
        "mma.sync.aligned.m16n8k16.row.col.f32.f16.f16.f32 "
        "{%0,%1,%2,%3}, {%4,%5,%6,%7}, {%8,%9}, {%0,%1,%2,%3};"
        : "+f"(d[0]), "+f"(d[1]), "+f"(d[2]), "+f"(d[3])
        : "r"(a[0]), "r"(a[1]), "r"(a[2]), "r"(a[3]), "r"(b0), "r"(b1));
}

// ---------------- convert: fp32 -> fp16 (x and W in one kernel) ----------------
__global__ __launch_bounds__(256) void cvt_kernel(const float4* __restrict__ x,
                                                  const float4* __restrict__ w) {
    const int n4 = (int)(((size_t)BATCH * IN_DIM) / 4);
    uint2* xh = reinterpret_cast<uint2*>(g_xh);
    uint2* wh = reinterpret_cast<uint2*>(g_wh);
    const int stride = gridDim.x * blockDim.x;
    for (int i = blockIdx.x * blockDim.x + threadIdx.x; i < 2 * n4; i += stride) {
        const bool isW = (i >= n4);
        const int j = isW ? i - n4 : i;
        float4 v = isW ? w[j] : x[j];
        __half2 p0 = make_half2(__float2half_rn(v.x), __float2half_rn(v.y));
        __half2 p1 = make_half2(__float2half_rn(v.z), __float2half_rn(v.w));
        uint2 r = make_uint2(*reinterpret_cast<uint32_t*>(&p0),
                             *reinterpret_cast<uint32_t*>(&p1));
        if (isW) wh[j] = r; else xh[j] = r;
    }
}

// ---------------- GEMM ----------------
// CTA tile 128x128, 128 threads (4 warps, 2x2), warp tile 64x64.
// K-chunk = 64 fp16, 3-stage cp.async pipeline (32 KB/stage, 96 KB/CTA).
static constexpr int MT = 128;
static constexpr int NT = 128;
static constexpr int KC = 64;
static constexpr int STAGES = 3;
static constexpr int NCHUNK = IN_DIM / KC;              // 64
static constexpr uint32_t ST_A = 0;                     // 128 rows x 128B = 16 KB
static constexpr uint32_t ST_B = 16384;                 // 128 rows x 128B = 16 KB
static constexpr uint32_t STAGE_BYTES = 32768;          // 32 KB
static constexpr uint32_t SMEM_TOTAL = STAGES * STAGE_BYTES;  // 96 KB

// SMEM tile: row pitch 128B (64 fp16), SW128-style swizzle: 16B-col ^= row&7
__device__ __forceinline__ uint32_t swz(int row, int c16) {
    return (uint32_t)(row * 128 + ((c16 ^ (row & 7)) << 4));
}

__global__ __launch_bounds__(128, 2) void gemm_fp16_kernel(const float* __restrict__ bias,
                                                           float* __restrict__ out) {
    extern __shared__ char smem[];
    const uint32_t sb = smem_to_u32(smem);
    const int tid = threadIdx.x;
    const int wid = tid >> 5;
    const int lid = tid & 31;
    const int wm = wid >> 1;          // 0..1 : M warp (64 rows)
    const int wn = wid & 1;           // 0..1 : N warp (64 cols)

    // CTA swizzle: width-16 super-columns -> concurrent CTAs stay L2-compact
    const int bid = blockIdx.x;
    const int bx = (bid & 15) | ((bid >> 9) << 4);
    const int by = (bid >> 4) & 31;
    const int m0 = by * MT;
    const int n0 = bx * NT;

    // ---- producer base+stride addressing ----
    // item i (i=0..7): row = (tid>>3) + 16*i, c16 = tid&7
    // (row&7) invariant under +16 -> swizzled dst stride is constant 2048.
    const int prow = tid >> 3, pc16 = tid & 7;
    const __half* srcA = g_xh + (size_t)(m0 + prow) * IN_DIM + pc16 * 8;
    const __half* srcB = g_wh + (size_t)(n0 + prow) * IN_DIM + pc16 * 8;
    const uint32_t pDst = swz(prow, pc16);
    const size_t rowStep = (size_t)16 * IN_DIM;

    // ---- ldmatrix per-thread precompute ----
    const int lrow = lid & 15;
    const uint32_t lcol = (uint32_t)(lid >> 4);
    uint32_t aOff[4], aXr[4], bOff[4], bXr[4];
#pragma unroll
    for (int mt = 0; mt < 4; mt++) {
        int r = wm * 64 + mt * 16 + lrow;
        aOff[mt] = (uint32_t)(r * 128);
        aXr[mt]  = (uint32_t)(r & 7);
    }
#pragma unroll
    for (int nt2 = 0; nt2 < 4; nt2++) {
        int r = wn * 64 + nt2 * 16 + lrow;
        bOff[nt2] = (uint32_t)(r * 128);
        bXr[nt2]  = (uint32_t)(r & 7);
    }

    float acc[4][8][4];
#pragma unroll
    for (int mt = 0; mt < 4; mt++)
#pragma unroll
        for (int nt = 0; nt < 8; nt++)
#pragma unroll
            for (int j = 0; j < 4; j++) acc[mt][nt][j] = 0.0f;

    // ---- prologue: fill STAGES-1 stages ----
#pragma unroll
    for (int c = 0; c < STAGES - 1; c++) {
        const uint32_t stg = sb + (uint32_t)c * STAGE_BYTES;
        const int k0 = c * KC;
#pragma unroll
        for (int i = 0; i < 8; i++) {
            cp16(stg + ST_A + pDst + i * 2048, srcA + k0 + i * rowStep);
            cp16(stg + ST_B + pDst + i * 2048, srcB + k0 + i * rowStep);
        }
        CP_COMMIT();
    }

    // ---- mainloop ----
    int s_cons = 0, s_prod = STAGES - 1;
    for (int c = 0; c < NCHUNK; c++) {
        CP_WAIT(STAGES - 2);
        __syncthreads();

        // issue loads for chunk c + STAGES-1
        if (c + STAGES - 1 < NCHUNK) {
            const uint32_t stg = sb + (uint32_t)s_prod * STAGE_BYTES;
            const int k0 = (c + STAGES - 1) * KC;
#pragma unroll
            for (int i = 0; i < 8; i++) {
                cp16(stg + ST_A + pDst + i * 2048, srcA + k0 + i * rowStep);
                cp16(stg + ST_B + pDst + i * 2048, srcB + k0 + i * rowStep);
            }
        }
        CP_COMMIT();

        // ---- compute on stage s_cons: 4 k16-steps, FULL A+B double-buffer ----
        const uint32_t stA = sb + (uint32_t)s_cons * STAGE_BYTES + ST_A;
        const uint32_t stB = sb + (uint32_t)s_cons * STAGE_BYTES + ST_B;

        uint32_t ah[2][4][4];     // [buf][mt][reg]
        uint32_t bh[2][4][4];     // [buf][nt2][reg]
#pragma unroll
        for (int mt = 0; mt < 4; mt++)
            ldmx4(ah[0][mt], stA + aOff[mt] + ((lcol ^ aXr[mt]) << 4));
#pragma unroll
        for (int nt2 = 0; nt2 < 4; nt2++)
            ldmx4(bh[0][nt2], stB + bOff[nt2] + ((lcol ^ bXr[nt2]) << 4));

#pragma unroll
        for (int ks = 0; ks < 4; ks++) {
            const int cur = ks & 1;
            // batch-prefetch ALL fragments for ks+1 (8 LDSM, MLP=8),
            // covered by the 32 MMAs below.
            if (ks < 3) {
                const uint32_t kcn = (uint32_t)(ks * 2 + 2) + lcol;
#pragma unroll
                for (int mt = 0; mt < 4; mt++)
                    ldmx4(ah[cur ^ 1][mt], stA + aOff[mt] + ((kcn ^ aXr[mt]) << 4));
#pragma unroll
                for (int nt2 = 0; nt2 < 4; nt2++)
                    ldmx4(bh[cur ^ 1][nt2], stB + bOff[nt2] + ((kcn ^ bXr[nt2]) << 4));
            }
            // 32 back-to-back MMAs on current fragments
#pragma unroll
            for (int nt2 = 0; nt2 < 4; nt2++)
#pragma unroll
                for (int mt = 0; mt < 4; mt++) {
                    mma16816(acc[mt][nt2 * 2],     ah[cur][mt], bh[cur][nt2][0], bh[cur][nt2][2]);
                    mma16816(acc[mt][nt2 * 2 + 1], ah[cur][mt], bh[cur][nt2][1], bh[cur][nt2][3]);
                }
        }
        if (++s_cons == STAGES) s_cons = 0;
        if (++s_prod == STAGES) s_prod = 0;
    }

    // ---- epilogue: bias + direct float2 stores ----
    const int gr = lid >> 2;
    const int gc = (lid & 3) * 2;
#pragma unroll
    for (int mt = 0; mt < 4; mt++) {
        const int rbase = m0 + wm * 64 + mt * 16 + gr;
#pragma unroll
        for (int nt = 0; nt < 8; nt++) {
            const int col = n0 + wn * 64 + nt * 8 + gc;
            const float b0 = __ldg(bias + col);
            const float b1 = __ldg(bias + col + 1);
            float2 v0 = make_float2(acc[mt][nt][0] + b0, acc[mt][nt][1] + b1);
            float2 v1 = make_float2(acc[mt][nt][2] + b0, acc[mt][nt][3] + b1);
            *reinterpret_cast<float2*>(out + (size_t)rbase * OUT_DIM + col) = v0;
            *reinterpret_cast<float2*>(out + (size_t)(rbase + 8) * OUT_DIM + col) = v1;
        }
    }
}

// ---------------- launch ----------------
extern "C" void kernel_launch(void* const* d_in, const int* in_sizes, int n_in,
                              void* d_out, int out_size) {
    (void)in_sizes; (void)n_in; (void)out_size;
    const float* x = (const float*)d_in[0];
    const float* W = (const float*)d_in[1];
    const float* b = (const float*)d_in[2];
    float* out = (float*)d_out;

    cvt_kernel<<<4096, 256>>>((const float4*)x, (const float4*)W);

    cudaFuncSetAttribute(gemm_fp16_kernel,
                         cudaFuncAttributeMaxDynamicSharedMemorySize, SMEM_TOTAL);
    const int nblocks = (BATCH / MT) * (OUT_DIM / NT);  // 1024
    gemm_fp16_kernel<<<nblocks, 128, SMEM_TOTAL>>>(b, out);
}

// round 15
// speedup vs baseline: 1.0321x; 1.0321x over previous
#include <cuda_runtime.h>
#include <cuda_fp16.h>
#include <cstdint>

// ============================================================
// out[4096,4096] = x[4096,4096] @ W^T[4096,4096] + b
// SINGLE fp16 GEMM:  out ≈ fp16(x) @ fp16(W)^T + b  (rel_err ~2.8e-4)
// mma.sync HMMA fp32-acc.
// 2 CTAs/SM x 4 warps, CTA tile 128x128, warp tile 64x64.
// R14: precomputed LDSM offsets (1-ADD addressing) +
//      cp.async issue spread across ks-steps.
// ============================================================

#define BATCH   4096
#define IN_DIM  4096
#define OUT_DIM 4096

__device__ __half g_xh[(size_t)BATCH * IN_DIM];
__device__ __half g_wh[(size_t)OUT_DIM * IN_DIM];

// ---------------- PTX helpers ----------------
__device__ __forceinline__ uint32_t smem_to_u32(const void* p) {
    uint32_t a;
    asm("{ .reg .u64 t; cvta.to.shared.u64 t, %1; cvt.u32.u64 %0, t; }" : "=r"(a) : "l"(p));
    return a;
}

__device__ __forceinline__ void cp16(uint32_t dst, const void* src) {
    asm volatile("cp.async.cg.shared.global [%0], [%1], 16;"
                 :: "r"(dst), "l"(__cvta_generic_to_global(src)) : "memory");
}

#define CP_COMMIT() asm volatile("cp.async.commit_group;" ::: "memory")
#define CP_WAIT(n)  asm volatile("cp.async.wait_group %0;" :: "n"(n) : "memory")

__device__ __forceinline__ void ldmx4(uint32_t* r, uint32_t addr) {
    asm volatile("ldmatrix.sync.aligned.m8n8.x4.shared.b16 {%0,%1,%2,%3}, [%4];"
                 : "=r"(r[0]), "=r"(r[1]), "=r"(r[2]), "=r"(r[3]) : "r"(addr));
}

__device__ __forceinline__ void mma16816(float* d, const uint32_t* a,
                                         uint32_t b0, uint32_t b1) {
    asm volatile(
        "mma.sync.aligned.m16n8k16.row.col.f32.f16.f16.f32 "
        "{%0,%1,%2,%3}, {%4,%5,%6,%7}, {%8,%9}, {%0,%1,%2,%3};"
        : "+f"(d[0]), "+f"(d[1]), "+f"(d[2]), "+f"(d[3])
        : "r"(a[0]), "r"(a[1]), "r"(a[2]), "r"(a[3]), "r"(b0), "r"(b1));
}

// ---------------- convert: fp32 -> fp16 (x and W in one kernel) ----------------
__global__ __launch_bounds__(256) void cvt_kernel(const float4* __restrict__ x,
                                                  const float4* __restrict__ w) {
    const int n4 = (int)(((size_t)BATCH * IN_DIM) / 4);
    uint2* xh = reinterpret_cast<uint2*>(g_xh);
    uint2* wh = reinterpret_cast<uint2*>(g_wh);
    const int stride = gridDim.x * blockDim.x;
    for (int i = blockIdx.x * blockDim.x + threadIdx.x; i < 2 * n4; i += stride) {
        const bool isW = (i >= n4);
        const int j = isW ? i - n4 : i;
        float4 v = isW ? w[j] : x[j];
        __half2 p0 = make_half2(__float2half_rn(v.x), __float2half_rn(v.y));
        __half2 p1 = make_half2(__float2half_rn(v.z), __float2half_rn(v.w));
        uint2 r = make_uint2(*reinterpret_cast<uint32_t*>(&p0),
                             *reinterpret_cast<uint32_t*>(&p1));
        if (isW) wh[j] = r; else xh[j] = r;
    }
}

// ---------------- GEMM ----------------
// CTA tile 128x128, 128 threads (4 warps, 2x2), warp tile 64x64.
// K-chunk = 64 fp16, 3-stage cp.async pipeline (32 KB/stage, 96 KB/CTA).
static constexpr int MT = 128;
static constexpr int NT = 128;
static constexpr int KC = 64;
static constexpr int STAGES = 3;
static constexpr int NCHUNK = IN_DIM / KC;              // 64
static constexpr uint32_t ST_A = 0;                     // 128 rows x 128B = 16 KB
static constexpr uint32_t ST_B = 16384;                 // 128 rows x 128B = 16 KB
static constexpr uint32_t STAGE_BYTES = 32768;          // 32 KB
static constexpr uint32_t SMEM_TOTAL = STAGES * STAGE_BYTES;  // 96 KB

// SMEM tile: row pitch 128B (64 fp16), SW128-style swizzle: 16B-col ^= row&7
__device__ __forceinline__ uint32_t swz(int row, int c16) {
    return (uint32_t)(row * 128 + ((c16 ^ (row & 7)) << 4));
}

__global__ __launch_bounds__(128, 2) void gemm_fp16_kernel(const float* __restrict__ bias,
                                                           float* __restrict__ out) {
    extern __shared__ char smem[];
    const uint32_t sb = smem_to_u32(smem);
    const int tid = threadIdx.x;
    const int wid = tid >> 5;
    const int lid = tid & 31;
    const int wm = wid >> 1;          // 0..1 : M warp (64 rows)
    const int wn = wid & 1;           // 0..1 : N warp (64 cols)

    // CTA swizzle: width-16 super-columns -> concurrent CTAs stay L2-compact
    const int bid = blockIdx.x;
    const int bx = (bid & 15) | ((bid >> 9) << 4);
    const int by = (bid >> 4) & 31;
    const int m0 = by * MT;
    const int n0 = bx * NT;

    // ---- producer base+stride addressing ----
    // item i (i=0..7): row = (tid>>3) + 16*i, c16 = tid&7
    // (row&7) invariant under +16 -> swizzled dst stride is constant 2048.
    const int prow = tid >> 3, pc16 = tid & 7;
    const __half* srcA = g_xh + (size_t)(m0 + prow) * IN_DIM + pc16 * 8;
    const __half* srcB = g_wh + (size_t)(n0 + prow) * IN_DIM + pc16 * 8;
    const uint32_t pDst = swz(prow, pc16);
    const size_t rowStep = (size_t)16 * IN_DIM;

    // ---- precomputed LDSM offsets: addr = stage_base + off  (1 ADD) ----
    // offA[ks][mt] folds ST_A(=0); offB[ks][nt2] folds ST_B.
    const int lrow = lid & 15;
    const uint32_t lcol = (uint32_t)(lid >> 4);
    uint32_t offA[4][4], offB[4][4];
#pragma unroll
    for (int ks = 0; ks < 4; ks++) {
        const uint32_t kc = (uint32_t)(ks * 2) + lcol;
#pragma unroll
        for (int mt = 0; mt < 4; mt++) {
            int r = wm * 64 + mt * 16 + lrow;
            offA[ks][mt] = ST_A + (uint32_t)(r * 128) + (((kc ^ (uint32_t)(r & 7))) << 4);
        }
#pragma unroll
        for (int nt2 = 0; nt2 < 4; nt2++) {
            int r = wn * 64 + nt2 * 16 + lrow;
            offB[ks][nt2] = ST_B + (uint32_t)(r * 128) + (((kc ^ (uint32_t)(r & 7))) << 4);
        }
    }

    float acc[4][8][4];
#pragma unroll
    for (int mt = 0; mt < 4; mt++)
#pragma unroll
        for (int nt = 0; nt < 8; nt++)
#pragma unroll
            for (int j = 0; j < 4; j++) acc[mt][nt][j] = 0.0f;

    // ---- prologue: fill STAGES-1 stages ----
#pragma unroll
    for (int c = 0; c < STAGES - 1; c++) {
        const uint32_t stg = sb + (uint32_t)c * STAGE_BYTES;
        const int k0 = c * KC;
#pragma unroll
        for (int i = 0; i < 8; i++) {
            cp16(stg + ST_A + pDst + i * 2048, srcA + k0 + i * rowStep);
            cp16(stg + ST_B + pDst + i * 2048, srcB + k0 + i * rowStep);
        }
        CP_COMMIT();
    }

    // ---- mainloop ----
    int s_cons = 0, s_prod = STAGES - 1;
    for (int c = 0; c < NCHUNK; c++) {
        // wait for stage s_cons data (all groups <= c retired), THEN barrier:
        // cross-thread cp.async visibility requires wait-before-sync.
        CP_WAIT(STAGES - 2);
        __syncthreads();

        const bool doProd = (c + STAGES - 1 < NCHUNK);
        const uint32_t pstg = sb + (uint32_t)s_prod * STAGE_BYTES;
        const int k0 = (c + STAGES - 1) * KC;

        const uint32_t stg = sb + (uint32_t)s_cons * STAGE_BYTES;

        uint32_t ah[2][4][4];     // [buf][mt][reg]
        uint32_t bh[2][4][4];     // [buf][nt2][reg]
#pragma unroll
        for (int mt = 0; mt < 4; mt++) ldmx4(ah[0][mt], stg + offA[0][mt]);
#pragma unroll
        for (int nt2 = 0; nt2 < 4; nt2++) ldmx4(bh[0][nt2], stg + offB[0][nt2]);

#pragma unroll
        for (int ks = 0; ks < 4; ks++) {
            const int cur = ks & 1;
            // batch-prefetch all fragments for ks+1 (covered by 32 MMAs below)
            if (ks < 3) {
#pragma unroll
                for (int mt = 0; mt < 4; mt++)
                    ldmx4(ah[cur ^ 1][mt], stg + offA[ks + 1][mt]);
#pragma unroll
                for (int nt2 = 0; nt2 < 4; nt2++)
                    ldmx4(bh[cur ^ 1][nt2], stg + offB[ks + 1][nt2]);
            }
            // spread producer issue: 2 A + 2 B cp.async per ks step
            if (doProd) {
                const int i0 = ks * 2, i1 = ks * 2 + 1;
                cp16(pstg + ST_A + pDst + i0 * 2048, srcA + k0 + i0 * rowStep);
                cp16(pstg + ST_A + pDst + i1 * 2048, srcA + k0 + i1 * rowStep);
                cp16(pstg + ST_B + pDst + i0 * 2048, srcB + k0 + i0 * rowStep);
                cp16(pstg + ST_B + pDst + i1 * 2048, srcB + k0 + i1 * rowStep);
            }
            // 32 back-to-back MMAs on current fragments
#pragma unroll
            for (int nt2 = 0; nt2 < 4; nt2++)
#pragma unroll
                for (int mt = 0; mt < 4; mt++) {
                    mma16816(acc[mt][nt2 * 2],     ah[cur][mt], bh[cur][nt2][0], bh[cur][nt2][2]);
                    mma16816(acc[mt][nt2 * 2 + 1], ah[cur][mt], bh[cur][nt2][1], bh[cur][nt2][3]);
                }
        }
        CP_COMMIT();

        if (++s_cons == STAGES) s_cons = 0;
        if (++s_prod == STAGES) s_prod = 0;
    }

    // ---- epilogue: bias + direct float2 stores ----
    const int gr = lid >> 2;
    const int gc = (lid & 3) * 2;
#pragma unroll
    for (int mt = 0; mt < 4; mt++) {
        const int rbase = m0 + wm * 64 + mt * 16 + gr;
#pragma unroll
        for (int nt = 0; nt < 8; nt++) {
            const int col = n0 + wn * 64 + nt * 8 + gc;
            const float b0 = __ldg(bias + col);
            const float b1 = __ldg(bias + col + 1);
            float2 v0 = make_float2(acc[mt][nt][0] + b0, acc[mt][nt][1] + b1);
            float2 v1 = make_float2(acc[mt][nt][2] + b0, acc[mt][nt][3] + b1);
            *reinterpret_cast<float2*>(out + (size_t)rbase * OUT_DIM + col) = v0;
            *reinterpret_cast<float2*>(out + (size_t)(rbase + 8) * OUT_DIM + col) = v1;
        }
    }
}

// ---------------- launch ----------------
extern "C" void kernel_launch(void* const* d_in, const int* in_sizes, int n_in,
                              void* d_out, int out_size) {
    (void)in_sizes; (void)n_in; (void)out_size;
    const float* x = (const float*)d_in[0];
    const float* W = (const float*)d_in[1];
    const float* b = (const float*)d_in[2];
    float* out = (float*)d_out;

    cvt_kernel<<<4096, 256>>>((const float4*)x, (const float4*)W);

    cudaFuncSetAttribute(gemm_fp16_kernel,
                         cudaFuncAttributeMaxDynamicSharedMemorySize, SMEM_TOTAL);
    const int nblocks = (BATCH / MT) * (OUT_DIM / NT);  // 1024
    gemm_fp16_kernel<<<nblocks, 128, SMEM_TOTAL>>>(b, out);
}

// round 16
// speedup vs baseline: 1.0437x; 1.0112x over previous
#include <cuda_runtime.h>
#include <cuda_fp16.h>
#include <cstdint>

// ============================================================
// out[4096,4096] = x[4096,4096] @ W^T[4096,4096] + b
// SINGLE fp16 GEMM:  out ≈ fp16(x) @ fp16(W)^T + b  (rel_err ~2.8e-4)
// mma.sync HMMA fp32-acc.
// 2 CTAs/SM x 4 warps, CTA tile 128x128, warp tile 64x64.
// R16: bias reg-prefetch, incremental producer pointers,
//      cp.async inside MMA burst, early commit.
// ============================================================

#define BATCH   4096
#define IN_DIM  4096
#define OUT_DIM 4096

__device__ __half g_xh[(size_t)BATCH * IN_DIM];
__device__ __half g_wh[(size_t)OUT_DIM * IN_DIM];

// ---------------- PTX helpers ----------------
__device__ __forceinline__ uint32_t smem_to_u32(const void* p) {
    uint32_t a;
    asm("{ .reg .u64 t; cvta.to.shared.u64 t, %1; cvt.u32.u64 %0, t; }" : "=r"(a) : "l"(p));
    return a;
}

__device__ __forceinline__ void cp16(uint32_t dst, const void* src) {
    asm volatile("cp.async.cg.shared.global [%0], [%1], 16;"
                 :: "r"(dst), "l"(__cvta_generic_to_global(src)) : "memory");
}

#define CP_COMMIT() asm volatile("cp.async.commit_group;" ::: "memory")
#define CP_WAIT(n)  asm volatile("cp.async.wait_group %0;" :: "n"(n) : "memory")

__device__ __forceinline__ void ldmx4(uint32_t* r, uint32_t addr) {
    asm volatile("ldmatrix.sync.aligned.m8n8.x4.shared.b16 {%0,%1,%2,%3}, [%4];"
                 : "=r"(r[0]), "=r"(r[1]), "=r"(r[2]), "=r"(r[3]) : "r"(addr));
}

__device__ __forceinline__ void mma16816(float* d, const uint32_t* a,
                                         uint32_t b0, uint32_t b1) {
    asm volatile(
        "mma.sync.aligned.m16n8k16.row.col.f32.f16.f16.f32 "
        "{%0,%1,%2,%3}, {%4,%5,%6,%7}, {%8,%9}, {%0,%1,%2,%3};"
        : "+f"(d[0]), "+f"(d[1]), "+f"(d[2]), "+f"(d[3])
        : "r"(a[0]), "r"(a[1]), "r"(a[2]), "r"(a[3]), "r"(b0), "r"(b1));
}

// ---------------- convert: fp32 -> fp16 (x and W in one kernel) ----------------
__global__ __launch_bounds__(256) void cvt_kernel(const float4* __restrict__ x,
                                                  const float4* __restrict__ w) {
    const int n4 = (int)(((size_t)BATCH * IN_DIM) / 4);
    uint2* xh = reinterpret_cast<uint2*>(g_xh);
    uint2* wh = reinterpret_cast<uint2*>(g_wh);
    const int stride = gridDim.x * blockDim.x;
    for (int i = blockIdx.x * blockDim.x + threadIdx.x; i < 2 * n4; i += stride) {
        const bool isW = (i >= n4);
        const int j = isW ? i - n4 : i;
        float4 v = isW ? w[j] : x[j];
        __half2 p0 = make_half2(__float2half_rn(v.x), __float2half_rn(v.y));
        __half2 p1 = make_half2(__float2half_rn(v.z), __float2half_rn(v.w));
        uint2 r = make_uint2(*reinterpret_cast<uint32_t*>(&p0),
                             *reinterpret_cast<uint32_t*>(&p1));
        if (isW) wh[j] = r; else xh[j] = r;
    }
}

// ---------------- GEMM ----------------
// CTA tile 128x128, 128 threads (4 warps, 2x2), warp tile 64x64.
// K-chunk = 64 fp16, 3-stage cp.async pipeline (32 KB/stage, 96 KB/CTA).
static constexpr int MT = 128;
static constexpr int NT = 128;
static constexpr int KC = 64;
static constexpr int STAGES = 3;
static constexpr int NCHUNK = IN_DIM / KC;              // 64
static constexpr uint32_t ST_A = 0;                     // 128 rows x 128B = 16 KB
static constexpr uint32_t ST_B = 16384;                 // 128 rows x 128B = 16 KB
static constexpr uint32_t STAGE_BYTES = 32768;          // 32 KB
static constexpr uint32_t SMEM_TOTAL = STAGES * STAGE_BYTES;  // 96 KB

// SMEM tile: row pitch 128B (64 fp16), SW128-style swizzle: 16B-col ^= row&7
__device__ __forceinline__ uint32_t swz(int row, int c16) {
    return (uint32_t)(row * 128 + ((c16 ^ (row & 7)) << 4));
}

__global__ __launch_bounds__(128, 2) void gemm_fp16_kernel(const float* __restrict__ bias,
                                                           float* __restrict__ out) {
    extern __shared__ char smem[];
    const uint32_t sb = smem_to_u32(smem);
    const int tid = threadIdx.x;
    const int wid = tid >> 5;
    const int lid = tid & 31;
    const int wm = wid >> 1;          // 0..1 : M warp (64 rows)
    const int wn = wid & 1;           // 0..1 : N warp (64 cols)

    // CTA swizzle: width-16 super-columns -> concurrent CTAs stay L2-compact
    const int bid = blockIdx.x;
    const int bx = (bid & 15) | ((bid >> 9) << 4);
    const int by = (bid >> 4) & 31;
    const int m0 = by * MT;
    const int n0 = bx * NT;

    // ---- producer base+stride addressing ----
    // item i (i=0..7): row = (tid>>3) + 16*i, c16 = tid&7
    // (row&7) invariant under +16 -> swizzled dst stride is constant 2048.
    const int prow = tid >> 3, pc16 = tid & 7;
    const __half* srcA = g_xh + (size_t)(m0 + prow) * IN_DIM + pc16 * 8;
    const __half* srcB = g_wh + (size_t)(n0 + prow) * IN_DIM + pc16 * 8;
    const uint32_t pDst = swz(prow, pc16);
    const size_t rowStep = (size_t)16 * IN_DIM;

    // ---- precomputed LDSM offsets: addr = stage_base + off  (1 ADD) ----
    const int lrow = lid & 15;
    const uint32_t lcol = (uint32_t)(lid >> 4);
    uint32_t offA[4][4], offB[4][4];
#pragma unroll
    for (int ks = 0; ks < 4; ks++) {
        const uint32_t kc = (uint32_t)(ks * 2) + lcol;
#pragma unroll
        for (int mt = 0; mt < 4; mt++) {
            int r = wm * 64 + mt * 16 + lrow;
            offA[ks][mt] = ST_A + (uint32_t)(r * 128) + (((kc ^ (uint32_t)(r & 7))) << 4);
        }
#pragma unroll
        for (int nt2 = 0; nt2 < 4; nt2++) {
            int r = wn * 64 + nt2 * 16 + lrow;
            offB[ks][nt2] = ST_B + (uint32_t)(r * 128) + (((kc ^ (uint32_t)(r & 7))) << 4);
        }
    }

    // ---- bias prefetch: 8 float2 per thread (epilogue columns) ----
    const int gr = lid >> 2;
    const int gc = (lid & 3) * 2;
    float2 bv[8];
#pragma unroll
    for (int nt = 0; nt < 8; nt++) {
        const int col = n0 + wn * 64 + nt * 8 + gc;
        bv[nt] = make_float2(__ldg(bias + col), __ldg(bias + col + 1));
    }

    float acc[4][8][4];
#pragma unroll
    for (int mt = 0; mt < 4; mt++)
#pragma unroll
        for (int nt = 0; nt < 8; nt++)
#pragma unroll
            for (int j = 0; j < 4; j++) acc[mt][nt][j] = 0.0f;

    // ---- prologue: fill STAGES-1 stages ----
#pragma unroll
    for (int c = 0; c < STAGES - 1; c++) {
        const uint32_t stg = sb + (uint32_t)c * STAGE_BYTES;
        const int k0 = c * KC;
#pragma unroll
        for (int i = 0; i < 8; i++) {
            cp16(stg + ST_A + pDst + i * 2048, srcA + k0 + i * rowStep);
            cp16(stg + ST_B + pDst + i * 2048, srcB + k0 + i * rowStep);
        }
        CP_COMMIT();
    }

    // ---- mainloop ----
    // incremental producer pointers (chunk c loads k-offset (c+2)*KC)
    const __half* pA = srcA + (size_t)(STAGES - 1) * KC;
    const __half* pB = srcB + (size_t)(STAGES - 1) * KC;

    int s_cons = 0, s_prod = STAGES - 1;
    for (int c = 0; c < NCHUNK; c++) {
        // wait for stage s_cons data, THEN barrier (wait-before-sync).
        CP_WAIT(STAGES - 2);
        __syncthreads();

        const bool doProd = (c + STAGES - 1 < NCHUNK);
        const uint32_t pstg = sb + (uint32_t)s_prod * STAGE_BYTES;
        const uint32_t stg  = sb + (uint32_t)s_cons * STAGE_BYTES;

        uint32_t ah[2][4][4];     // [buf][mt][reg]
        uint32_t bh[2][4][4];     // [buf][nt2][reg]
#pragma unroll
        for (int mt = 0; mt < 4; mt++) ldmx4(ah[0][mt], stg + offA[0][mt]);
#pragma unroll
        for (int nt2 = 0; nt2 < 4; nt2++) ldmx4(bh[0][nt2], stg + offB[0][nt2]);

#pragma unroll
        for (int ks = 0; ks < 4; ks++) {
            const int cur = ks & 1;
            // batch-prefetch all fragments for ks+1 (covered by 32 MMAs below)
            if (ks < 3) {
#pragma unroll
                for (int mt = 0; mt < 4; mt++)
                    ldmx4(ah[cur ^ 1][mt], stg + offA[ks + 1][mt]);
#pragma unroll
                for (int nt2 = 0; nt2 < 4; nt2++)
                    ldmx4(bh[cur ^ 1][nt2], stg + offB[ks + 1][nt2]);
            }
            // first 8 MMAs (nt2=0) start the tensor burst immediately
#pragma unroll
            for (int mt = 0; mt < 4; mt++) {
                mma16816(acc[mt][0], ah[cur][mt], bh[cur][0][0], bh[cur][0][2]);
                mma16816(acc[mt][1], ah[cur][mt], bh[cur][0][1], bh[cur][0][3]);
            }
            // producer cp.async issued while tensor pipe is busy
            if (doProd) {
                const int i0 = ks * 2, i1 = ks * 2 + 1;
                cp16(pstg + ST_A + pDst + i0 * 2048, pA + i0 * rowStep);
                cp16(pstg + ST_A + pDst + i1 * 2048, pA + i1 * rowStep);
                cp16(pstg + ST_B + pDst + i0 * 2048, pB + i0 * rowStep);
                cp16(pstg + ST_B + pDst + i1 * 2048, pB + i1 * rowStep);
            }
            if (ks == 3) CP_COMMIT();   // early commit: group retires sooner
            // remaining 24 MMAs
#pragma unroll
            for (int nt2 = 1; nt2 < 4; nt2++)
#pragma unroll
                for (int mt = 0; mt < 4; mt++) {
                    mma16816(acc[mt][nt2 * 2],     ah[cur][mt], bh[cur][nt2][0], bh[cur][nt2][2]);
                    mma16816(acc[mt][nt2 * 2 + 1], ah[cur][mt], bh[cur][nt2][1], bh[cur][nt2][3]);
                }
        }

        pA += KC;
        pB += KC;
        if (++s_cons == STAGES) s_cons = 0;
        if (++s_prod == STAGES) s_prod = 0;
    }

    // ---- epilogue: prefetched bias + direct float2 stores ----
#pragma unroll
    for (int mt = 0; mt < 4; mt++) {
        const int rbase = m0 + wm * 64 + mt * 16 + gr;
#pragma unroll
        for (int nt = 0; nt < 8; nt++) {
            const int col = n0 + wn * 64 + nt * 8 + gc;
            float2 v0 = make_float2(acc[mt][nt][0] + bv[nt].x, acc[mt][nt][1] + bv[nt].y);
            float2 v1 = make_float2(acc[mt][nt][2] + bv[nt].x, acc[mt][nt][3] + bv[nt].y);
            *reinterpret_cast<float2*>(out + (size_t)rbase * OUT_DIM + col) = v0;
            *reinterpret_cast<float2*>(out + (size_t)(rbase + 8) * OUT_DIM + col) = v1;
        }
    }
}

// ---------------- launch ----------------
extern "C" void kernel_launch(void* const* d_in, const int* in_sizes, int n_in,
                              void* d_out, int out_size) {
    (void)in_sizes; (void)n_in; (void)out_size;
    const float* x = (const float*)d_in[0];
    const float* W = (const float*)d_in[1];
    const float* b = (const float*)d_in[2];
    float* out = (float*)d_out;

    cvt_kernel<<<4096, 256>>>((const float4*)x, (const float4*)W);

    cudaFuncSetAttribute(gemm_fp16_kernel,
                         cudaFuncAttributeMaxDynamicSharedMemorySize, SMEM_TOTAL);
    const int nblocks = (BATCH / MT) * (OUT_DIM / NT);  // 1024
    gemm_fp16_kernel<<<nblocks, 128, SMEM_TOTAL>>>(b, out);
}